// round 2
// baseline (speedup 1.0000x reference)
#include <cuda_runtime.h>
#include <cuda_bf16.h>
#include <cstdint>

#define N_NODES 100000
#define N_EDGES 1250000
#define D_IN 32
#define H 64
#define EPS 1e-5f

// scratch for hidden features h [N_NODES, H]
__device__ float g_h[(size_t)N_NODES * H];

// ---------------------------------------------------------------------------
// Kernel 1: node MLP  h = relu(LN(relu(LN(x@W1+b1))@W2+b2))
// 256 threads/block = 4 nodes x 64 features. Weights staged in shared.
// Writes h to g_h and also initializes out = h (aggr added later).
// ---------------------------------------------------------------------------
__global__ __launch_bounds__(256, 8)
void mlp_kernel(const float* __restrict__ x,
                const float* __restrict__ W1, const float* __restrict__ b1,
                const float* __restrict__ g1, const float* __restrict__ be1,
                const float* __restrict__ W2, const float* __restrict__ b2,
                const float* __restrict__ g2, const float* __restrict__ be2,
                float* __restrict__ h_out, float* __restrict__ out)
{
    __shared__ float sW1[D_IN * H];   // 8 KB
    __shared__ float sW2[H * H];      // 16 KB
    __shared__ float sb1[H], sg1[H], sbe1[H];
    __shared__ float sb2[H], sg2[H], sbe2[H];
    __shared__ float sx[4][D_IN];
    __shared__ float sh1[4][H];
    __shared__ float sred[4][2][2];   // [node][warp-half][sum, sumsq]

    const int tid = threadIdx.x;

    for (int i = tid; i < D_IN * H; i += 256) sW1[i] = W1[i];
    for (int i = tid; i < H * H;    i += 256) sW2[i] = W2[i];
    if (tid < H) {
        sb1[tid] = b1[tid]; sg1[tid] = g1[tid]; sbe1[tid] = be1[tid];
        sb2[tid] = b2[tid]; sg2[tid] = g2[tid]; sbe2[tid] = be2[tid];
    }
    __syncthreads();

    const int n_local = tid >> 6;       // 0..3  node within block-chunk
    const int j       = tid & 63;       // feature index 0..63
    const int half    = (tid >> 5) & 1; // which warp-half of this node
    const int lane    = tid & 31;

    const int n_chunks = (N_NODES + 3) >> 2;
    for (int chunk = blockIdx.x; chunk < n_chunks; chunk += gridDim.x) {
        const int node = chunk * 4 + n_local;

        // stage x for the 4 nodes of this chunk
        if (tid < 128) {
            int nn = tid >> 5, kk = tid & 31;
            int gn = chunk * 4 + nn;
            sx[nn][kk] = (gn < N_NODES) ? x[(size_t)gn * D_IN + kk] : 0.f;
        }
        __syncthreads();

        // ---- layer 1: Linear(32->64) ----
        float acc = sb1[j];
        #pragma unroll
        for (int k = 0; k < D_IN; k++)
            acc = fmaf(sx[n_local][k], sW1[k * H + j], acc);

        // LN reduce over 64 features (2 warp-halves per node)
        float s = acc, sq = acc * acc;
        #pragma unroll
        for (int o = 16; o > 0; o >>= 1) {
            s  += __shfl_down_sync(0xFFFFFFFFu, s,  o);
            sq += __shfl_down_sync(0xFFFFFFFFu, sq, o);
        }
        if (lane == 0) { sred[n_local][half][0] = s; sred[n_local][half][1] = sq; }
        __syncthreads();
        float sum   = sred[n_local][0][0] + sred[n_local][1][0];
        float sumsq = sred[n_local][0][1] + sred[n_local][1][1];
        float mu  = sum * (1.f / H);
        float var = sumsq * (1.f / H) - mu * mu;
        float inv = rsqrtf(var + EPS);
        float h1 = fmaxf(fmaf((acc - mu) * inv, sg1[j], sbe1[j]), 0.f);
        sh1[n_local][j] = h1;
        __syncthreads();

        // ---- layer 2: Linear(64->64) ----
        float acc2 = sb2[j];
        #pragma unroll
        for (int k = 0; k < H; k++)
            acc2 = fmaf(sh1[n_local][k], sW2[k * H + j], acc2);

        s = acc2; sq = acc2 * acc2;
        #pragma unroll
        for (int o = 16; o > 0; o >>= 1) {
            s  += __shfl_down_sync(0xFFFFFFFFu, s,  o);
            sq += __shfl_down_sync(0xFFFFFFFFu, sq, o);
        }
        if (lane == 0) { sred[n_local][half][0] = s; sred[n_local][half][1] = sq; }
        __syncthreads();
        sum   = sred[n_local][0][0] + sred[n_local][1][0];
        sumsq = sred[n_local][0][1] + sred[n_local][1][1];
        mu  = sum * (1.f / H);
        var = sumsq * (1.f / H) - mu * mu;
        inv = rsqrtf(var + EPS);
        float h2 = fmaxf(fmaf((acc2 - mu) * inv, sg2[j], sbe2[j]), 0.f);

        if (node < N_NODES) {
            h_out[(size_t)node * H + j] = h2;
            out[(size_t)node * H + j]   = h2;   // init out = h
        }
        __syncthreads();  // protect sx/sh1/sred for next chunk
    }
}

// ---------------------------------------------------------------------------
// Kernel 2: edge scatter   out[row] += h[col]
// 16 threads per edge, each handles one float4 (16B). Vector reduction
// (red.global.add.v4.f32) — no return value, 1/4 the atomic op count.
// edge_index is int32 (JAX x64 is disabled; jnp.int64 request downcasts).
// ---------------------------------------------------------------------------
__global__ __launch_bounds__(256)
void edge_kernel(const int* __restrict__ ei,
                 const float4* __restrict__ h4,
                 float* __restrict__ out)
{
    long long idx = (long long)blockIdx.x * blockDim.x + threadIdx.x;
    int  lane16 = (int)(idx & 15);
    long long e = idx >> 4;
    if (e >= N_EDGES) return;

    int row = ei[e];            // destination
    int col = ei[N_EDGES + e];  // source
    if ((unsigned)row >= N_NODES || (unsigned)col >= N_NODES) return;  // dtype guard

    float4 v = h4[(long long)col * 16 + lane16];
    float* p = out + (long long)row * H + lane16 * 4;
    asm volatile("red.global.add.v4.f32 [%0], {%1,%2,%3,%4};"
                 :: "l"(p), "f"(v.x), "f"(v.y), "f"(v.z), "f"(v.w)
                 : "memory");
}

// ---------------------------------------------------------------------------
extern "C" void kernel_launch(void* const* d_in, const int* in_sizes, int n_in,
                              void* d_out, int out_size)
{
    const float* x   = (const float*)d_in[0];
    const int*   ei  = (const int*)d_in[1];
    const float* W1  = (const float*)d_in[2];
    const float* b1  = (const float*)d_in[3];
    const float* g1  = (const float*)d_in[4];
    const float* be1 = (const float*)d_in[5];
    const float* W2  = (const float*)d_in[6];
    const float* b2  = (const float*)d_in[7];
    const float* g2  = (const float*)d_in[8];
    const float* be2 = (const float*)d_in[9];
    float* out = (float*)d_out;

    float* h_buf;
    cudaGetSymbolAddress((void**)&h_buf, g_h);

    // Kernel 1: MLP + out init
    mlp_kernel<<<1184, 256>>>(x, W1, b1, g1, be1, W2, b2, g2, be2, h_buf, out);

    // Kernel 2: edge gather + vector scatter-add
    long long total = (long long)N_EDGES * 16;
    int blocks = (int)((total + 255) / 256);
    edge_kernel<<<blocks, 256>>>(ei, (const float4*)h_buf, out);
}